// round 9
// baseline (speedup 1.0000x reference)
#include <cuda_runtime.h>
#include <cuda_fp16.h>

#define NN 100000
#define NE 1600000
#define DD 64
#define SLOT 64          // fixed edge slots per node; P(deg>64) ~ 1e-19

// ---- scratch (static device globals; no allocation) ----
__device__ __half g_xa[NN * DD];         // prescaled activations x' = dinv*x (ping)
__device__ __half g_xb[NN * DD];         // (pong)
__device__ int    g_cnt[NN];             // in-degree
__device__ int    g_csrc[NN * SLOT];     // src ids bucketed by dst

__device__ __forceinline__ unsigned pk2(float a, float b) {
    __half2 h = __floats2half2_rn(a, b);
    return *reinterpret_cast<unsigned*>(&h);
}

// ---------------- fill: bucket src ids by dst ----------------
__global__ __launch_bounds__(256) void k_fill(const int* __restrict__ src,
                                              const int* __restrict__ dst) {
    int i = blockIdx.x * blockDim.x + threadIdx.x;
    int e0 = i * 4;
    if (e0 + 3 < NE) {
        int4 s4 = *(const int4*)(src + e0);
        int4 d4 = *(const int4*)(dst + e0);
        int p;
        p = atomicAdd(&g_cnt[d4.x], 1); if (p < SLOT) g_csrc[(d4.x << 6) + p] = s4.x;
        p = atomicAdd(&g_cnt[d4.y], 1); if (p < SLOT) g_csrc[(d4.y << 6) + p] = s4.y;
        p = atomicAdd(&g_cnt[d4.z], 1); if (p < SLOT) g_csrc[(d4.z << 6) + p] = s4.z;
        p = atomicAdd(&g_cnt[d4.w], 1); if (p < SLOT) g_csrc[(d4.w << 6) + p] = s4.w;
    } else {
        for (int e = e0; e < NE; e++) {
            int d = dst[e];
            int p = atomicAdd(&g_cnt[d], 1);
            if (p < SLOT) g_csrc[(d << 6) + p] = src[e];
        }
    }
}

// ---------------- prescale: x' = dinv * z (fp32 -> fp16) ----------------
__global__ __launch_bounds__(256) void k_prescale(const float* __restrict__ z,
                                                  __half* __restrict__ xp) {
    int i = blockIdx.x * blockDim.x + threadIdx.x;   // one uint4 (8 halves) per thread
    if (i >= NN * 8) return;
    int node = i >> 3;
    float dv = rsqrtf((float)__ldg(&g_cnt[node]) + 1.0f);
    const float4* zp = (const float4*)(z + (size_t)i * 8);
    float4 lo = __ldg(zp), hi = __ldg(zp + 1);
    uint4 v;
    v.x = pk2(dv * lo.x, dv * lo.y); v.y = pk2(dv * lo.z, dv * lo.w);
    v.z = pk2(dv * hi.x, dv * hi.y); v.w = pk2(dv * hi.z, dv * hi.w);
    ((uint4*)xp)[i] = v;
}

// ---------------- MMA helpers ----------------
__device__ __forceinline__ void ldsm_x4(unsigned &r0, unsigned &r1, unsigned &r2, unsigned &r3, unsigned addr) {
    asm volatile("ldmatrix.sync.aligned.m8n8.x4.shared.b16 {%0,%1,%2,%3}, [%4];\n"
                 : "=r"(r0), "=r"(r1), "=r"(r2), "=r"(r3) : "r"(addr));
}
__device__ __forceinline__ void ldsm_x2_t(unsigned &r0, unsigned &r1, unsigned addr) {
    asm volatile("ldmatrix.sync.aligned.m8n8.x2.trans.shared.b16 {%0,%1}, [%2];\n"
                 : "=r"(r0), "=r"(r1) : "r"(addr));
}
__device__ __forceinline__ void mma16816(float &c0, float &c1, float &c2, float &c3,
                                         unsigned a0, unsigned a1, unsigned a2, unsigned a3,
                                         unsigned b0, unsigned b1) {
    asm volatile("mma.sync.aligned.m16n8k16.row.col.f32.f16.f16.f32 "
                 "{%0,%1,%2,%3},{%4,%5,%6,%7},{%8,%9},{%0,%1,%2,%3};\n"
                 : "+f"(c0), "+f"(c1), "+f"(c2), "+f"(c3)
                 : "r"(a0), "r"(a1), "r"(a2), "r"(a3), "r"(b0), "r"(b1));
}

#define US_LD 72   // halves per row; 144B stride -> conflict-free ldmatrix
#define WS_LD 72

// fold one uint4 of half2 pairs into fp32 acc (8 cvt + 8 add)
__device__ __forceinline__ void fold8(float* acc, uint4 v) {
    float2 f;
    f = __half22float2(*(__half2*)&v.x); acc[0] += f.x; acc[1] += f.y;
    f = __half22float2(*(__half2*)&v.y); acc[2] += f.x; acc[3] += f.y;
    f = __half22float2(*(__half2*)&v.z); acc[4] += f.x; acc[5] += f.y;
    f = __half22float2(*(__half2*)&v.w); acc[6] += f.x; acc[7] += f.y;
}

// ---------------- fused layer: u = D^-1/2(A+I)D^-1/2 x ; y = uW + b ----------------
// Block: 256 threads, 32 nodes. Gather: each WARP processes its 4 nodes' edges
// as ONE flat list (length ~Poisson(64)) consumed 4-at-a-time by the 4
// subgroups of 8 lanes; per-node fp32 accumulators in registers, cross-subgroup
// shfl reduction at the end. Keeps 4 edges per warp-LDG (1 line/edge) while
// cutting tail imbalance from max-of-32 Poisson(16) to max-of-8 Poisson(64).
template <int FINAL>
__global__ __launch_bounds__(256) void k_layer(const __half* __restrict__ xp,
                                               const float* __restrict__ W,
                                               const float* __restrict__ b,
                                               void* __restrict__ outv) {
    __shared__ __align__(16) __half Us[32 * US_LD];
    __shared__ __align__(16) __half Ws[64 * WS_LD];
    int tid = threadIdx.x;
    int node0 = blockIdx.x * 32;

    // load W (fp32 -> fp16 smem)
    #pragma unroll
    for (int i = tid; i < 512; i += 256) {
        int r = i >> 3, cg = i & 7;
        const float4* wp = (const float4*)(W + r * 64 + cg * 8);
        float4 lo = __ldg(wp), hi = __ldg(wp + 1);
        uint4 v;
        v.x = pk2(lo.x, lo.y); v.y = pk2(lo.z, lo.w);
        v.z = pk2(hi.x, hi.y); v.w = pk2(hi.z, hi.w);
        *(uint4*)&Ws[r * WS_LD + cg * 8] = v;
    }

    int warp = tid >> 5, lane = tid & 31;

    // ---- gather phase ----
    {
        const uint4* hv = (const uint4*)xp;
        int nb = node0 + warp * 4;             // warp's 4 nodes (NN % 32 == 0)
        int sg = lane >> 3;                    // edge-parallel subgroup 0..3
        int sl = lane & 7;                     // 16B slice within row

        int c0 = __ldg(&g_cnt[nb + 0]); int l0 = c0 < SLOT ? c0 : SLOT;
        int c1 = __ldg(&g_cnt[nb + 1]); int l1 = c1 < SLOT ? c1 : SLOT;
        int c2 = __ldg(&g_cnt[nb + 2]); int l2 = c2 < SLOT ? c2 : SLOT;
        int c3 = __ldg(&g_cnt[nb + 3]); int l3 = c3 < SLOT ? c3 : SLOT;
        int p1 = l0, p2 = l0 + l1, p3 = p2 + l2, L = p3 + l3;

        float acc0[8], acc1[8], acc2[8], acc3[8];
        #pragma unroll
        for (int j = 0; j < 8; j++) { acc0[j] = 0.f; acc1[j] = 0.f; acc2[j] = 0.f; acc3[j] = 0.f; }

        // self term: subgroup sg loads row nb+sg (counted once after reduction)
        {
            uint4 v = __ldg(&hv[((size_t)(nb + sg) << 3) + sl]);
            if (sg == 0) fold8(acc0, v);
            else if (sg == 1) fold8(acc1, v);
            else if (sg == 2) fold8(acc2, v);
            else fold8(acc3, v);
        }

        for (int t = 0; t < L; t += 4) {
            int e = t + sg;
            bool valid = e < L;
            int o = (e >= p1) + (e >= p2) + (e >= p3);
            int pb = (o == 0) ? 0 : (o == 1) ? p1 : (o == 2) ? p2 : p3;
            int slot = e - pb;
            if (valid) {
                int idx = __ldg(&g_csrc[((nb + o) << 6) + slot]);
                uint4 v = __ldg(&hv[((size_t)idx << 3) + sl]);
                // owner chain: warp-uniform on runs (node-major order) -> one path
                if (o == 0) fold8(acc0, v);
                else if (o == 1) fold8(acc1, v);
                else if (o == 2) fold8(acc2, v);
                else fold8(acc3, v);
            }
        }

        // cross-subgroup reduction (lane bits 3,4)
        #pragma unroll
        for (int j = 0; j < 8; j++) {
            acc0[j] += __shfl_xor_sync(0xffffffffu, acc0[j], 8);
            acc0[j] += __shfl_xor_sync(0xffffffffu, acc0[j], 16);
            acc1[j] += __shfl_xor_sync(0xffffffffu, acc1[j], 8);
            acc1[j] += __shfl_xor_sync(0xffffffffu, acc1[j], 16);
            acc2[j] += __shfl_xor_sync(0xffffffffu, acc2[j], 8);
            acc2[j] += __shfl_xor_sync(0xffffffffu, acc2[j], 16);
            acc3[j] += __shfl_xor_sync(0xffffffffu, acc3[j], 8);
            acc3[j] += __shfl_xor_sync(0xffffffffu, acc3[j], 16);
        }

        // write: subgroup sg writes node nb+sg (lane sl -> cols [sl*8, sl*8+8))
        {
            float* a = (sg == 0) ? acc0 : (sg == 1) ? acc1 : (sg == 2) ? acc2 : acc3;
            int cc = (sg == 0) ? c0 : (sg == 1) ? c1 : (sg == 2) ? c2 : c3;
            float dv = rsqrtf((float)cc + 1.0f);
            uint4 u;
            u.x = pk2(dv * a[0], dv * a[1]);
            u.y = pk2(dv * a[2], dv * a[3]);
            u.z = pk2(dv * a[4], dv * a[5]);
            u.w = pk2(dv * a[6], dv * a[7]);
            *(uint4*)&Us[(warp * 4 + sg) * US_LD + sl * 8] = u;
        }
    }
    __syncthreads();

    // ---- matmul phase: 8 warps, warp = 16 rows x 16 cols ----
    int m0 = (warp & 1) * 16;
    int c0col = (warp >> 1) * 16;
    int g = lane >> 2, tig = lane & 3;

    unsigned us_base = (unsigned)__cvta_generic_to_shared(Us);
    unsigned ws_base = (unsigned)__cvta_generic_to_shared(Ws);

    float c[2][4];
    c[0][0] = c[0][1] = c[0][2] = c[0][3] = 0.f;
    c[1][0] = c[1][1] = c[1][2] = c[1][3] = 0.f;

    #pragma unroll
    for (int kc = 0; kc < 4; kc++) {
        unsigned a0, a1, a2, a3;
        unsigned aaddr = us_base + (m0 + (lane & 15)) * (US_LD * 2) + kc * 32 + (lane >> 4) * 16;
        ldsm_x4(a0, a1, a2, a3, aaddr);
        #pragma unroll
        for (int nt = 0; nt < 2; nt++) {
            unsigned b0, b1;
            unsigned baddr = ws_base + (kc * 16 + (lane & 15)) * (WS_LD * 2) + (c0col + nt * 8) * 2;
            ldsm_x2_t(b0, b1, baddr);
            mma16816(c[nt][0], c[nt][1], c[nt][2], c[nt][3], a0, a1, a2, a3, b0, b1);
        }
    }

    // ---- epilogue ----
    int r0 = node0 + m0 + g;
    int r1 = r0 + 8;
    if (FINAL) {
        float* out = (float*)outv;
        #pragma unroll
        for (int nt = 0; nt < 2; nt++) {
            int col = c0col + nt * 8 + tig * 2;
            float b0v = __ldg(&b[col]), b1v = __ldg(&b[col + 1]);
            *(float2*)&out[(size_t)r0 * DD + col] = make_float2(c[nt][0] + b0v, c[nt][1] + b1v);
            *(float2*)&out[(size_t)r1 * DD + col] = make_float2(c[nt][2] + b0v, c[nt][3] + b1v);
        }
    } else {
        __half* out = (__half*)outv;
        float dv0 = rsqrtf((float)__ldg(&g_cnt[r0]) + 1.0f);
        float dv1 = rsqrtf((float)__ldg(&g_cnt[r1]) + 1.0f);
        #pragma unroll
        for (int nt = 0; nt < 2; nt++) {
            int col = c0col + nt * 8 + tig * 2;
            float b0v = __ldg(&b[col]), b1v = __ldg(&b[col + 1]);
            float v00 = fmaxf(c[nt][0] + b0v, 0.f), v01 = fmaxf(c[nt][1] + b1v, 0.f);
            float v10 = fmaxf(c[nt][2] + b0v, 0.f), v11 = fmaxf(c[nt][3] + b1v, 0.f);
            *(unsigned*)&out[(size_t)r0 * DD + col] = pk2(dv0 * v00, dv0 * v01);
            *(unsigned*)&out[(size_t)r1 * DD + col] = pk2(dv1 * v10, dv1 * v11);
        }
    }
}

// ---------------- launch ----------------
extern "C" void kernel_launch(void* const* d_in, const int* in_sizes, int n_in,
                              void* d_out, int out_size) {
    const float* z   = (const float*)d_in[0];
    const int*   src = (const int*)d_in[1];
    const int*   dst = (const int*)d_in[2];
    const float* W1  = (const float*)d_in[3];
    const float* b1  = (const float*)d_in[4];
    const float* W2  = (const float*)d_in[5];
    const float* b2  = (const float*)d_in[6];
    const float* W3  = (const float*)d_in[7];
    const float* b3  = (const float*)d_in[8];
    float* out = (float*)d_out;

    __half *xa, *xb; int* cntp;
    cudaGetSymbolAddress((void**)&xa,   g_xa);
    cudaGetSymbolAddress((void**)&xb,   g_xb);
    cudaGetSymbolAddress((void**)&cntp, g_cnt);

    const int gridFill = (NE / 4 + 255) / 256;      // 1563
    const int gridPS   = (NN * 8 + 255) / 256;      // 3125
    const int gridL    = NN / 32;                   // 3125

    cudaMemsetAsync(cntp, 0, NN * sizeof(int));
    k_fill<<<gridFill, 256>>>(src, dst);
    k_prescale<<<gridPS, 256>>>(z, xa);

    k_layer<0><<<gridL, 256>>>(xa, W1, b1, xb);
    k_layer<0><<<gridL, 256>>>(xb, W2, b2, xa);
    k_layer<1><<<gridL, 256>>>(xa, W3, b3, out);
}

// round 10
// speedup vs baseline: 1.9036x; 1.9036x over previous
#include <cuda_runtime.h>
#include <cuda_fp16.h>

#define NN 100000
#define NE 1600000
#define DD 64
#define SLOT 64          // fixed edge slots per node; P(deg>64) ~ 1e-19

#define US_LD 72   // halves per row; 144B stride -> conflict-free ldmatrix
#define WS_LD 72

// ---- scratch (static device globals; no allocation) ----
__device__ __half g_xa[NN * DD];         // prescaled activations x' = dinv*x (ping)
__device__ __half g_xb[NN * DD];         // (pong)
__device__ int    g_cnt[NN];             // in-degree
__device__ int    g_csrc[NN * SLOT];     // src ids bucketed by dst
__device__ __half g_w16[3][64 * WS_LD];  // W in fp16, padded ldmatrix layout

__device__ __forceinline__ unsigned pk2(float a, float b) {
    __half2 h = __floats2half2_rn(a, b);
    return *reinterpret_cast<unsigned*>(&h);
}

// ---------------- fill: bucket src ids by dst ----------------
__global__ __launch_bounds__(256) void k_fill(const int* __restrict__ src,
                                              const int* __restrict__ dst) {
    int i = blockIdx.x * blockDim.x + threadIdx.x;
    int e0 = i * 4;
    if (e0 + 3 < NE) {
        int4 s4 = *(const int4*)(src + e0);
        int4 d4 = *(const int4*)(dst + e0);
        int p;
        p = atomicAdd(&g_cnt[d4.x], 1); if (p < SLOT) g_csrc[(d4.x << 6) + p] = s4.x;
        p = atomicAdd(&g_cnt[d4.y], 1); if (p < SLOT) g_csrc[(d4.y << 6) + p] = s4.y;
        p = atomicAdd(&g_cnt[d4.z], 1); if (p < SLOT) g_csrc[(d4.z << 6) + p] = s4.z;
        p = atomicAdd(&g_cnt[d4.w], 1); if (p < SLOT) g_csrc[(d4.w << 6) + p] = s4.w;
    } else {
        for (int e = e0; e < NE; e++) {
            int d = dst[e];
            int p = atomicAdd(&g_cnt[d], 1);
            if (p < SLOT) g_csrc[(d << 6) + p] = src[e];
        }
    }
}

// ---------------- W convert: 3x (64x64 fp32 -> padded [64][72] fp16) ----------------
__global__ __launch_bounds__(256) void k_wcvt(const float* __restrict__ W1,
                                              const float* __restrict__ W2,
                                              const float* __restrict__ W3) {
    const float* Wsrc = (blockIdx.x == 0) ? W1 : (blockIdx.x == 1) ? W2 : W3;
    __half* Wdst = g_w16[blockIdx.x];
    for (int i = threadIdx.x; i < 512; i += 256) {
        int r = i >> 3, cg = i & 7;
        const float4* wp = (const float4*)(Wsrc + r * 64 + cg * 8);
        float4 lo = __ldg(wp), hi = __ldg(wp + 1);
        uint4 v;
        v.x = pk2(lo.x, lo.y); v.y = pk2(lo.z, lo.w);
        v.z = pk2(hi.x, hi.y); v.w = pk2(hi.z, hi.w);
        *(uint4*)&Wdst[r * WS_LD + cg * 8] = v;
    }
}

// ---------------- prescale: x' = dinv * z (fp32 -> fp16) ----------------
__global__ __launch_bounds__(256) void k_prescale(const float* __restrict__ z,
                                                  __half* __restrict__ xp) {
    int i = blockIdx.x * blockDim.x + threadIdx.x;   // one uint4 (8 halves) per thread
    if (i >= NN * 8) return;
    int node = i >> 3;
    float dv = rsqrtf((float)__ldg(&g_cnt[node]) + 1.0f);
    const float4* zp = (const float4*)(z + (size_t)i * 8);
    float4 lo = __ldg(zp), hi = __ldg(zp + 1);
    uint4 v;
    v.x = pk2(dv * lo.x, dv * lo.y); v.y = pk2(dv * lo.z, dv * lo.w);
    v.z = pk2(dv * hi.x, dv * hi.y); v.w = pk2(dv * hi.z, dv * hi.w);
    ((uint4*)xp)[i] = v;
}

// ---------------- MMA helpers ----------------
__device__ __forceinline__ void ldsm_x4(unsigned &r0, unsigned &r1, unsigned &r2, unsigned &r3, unsigned addr) {
    asm volatile("ldmatrix.sync.aligned.m8n8.x4.shared.b16 {%0,%1,%2,%3}, [%4];\n"
                 : "=r"(r0), "=r"(r1), "=r"(r2), "=r"(r3) : "r"(addr));
}
__device__ __forceinline__ void ldsm_x2_t(unsigned &r0, unsigned &r1, unsigned addr) {
    asm volatile("ldmatrix.sync.aligned.m8n8.x2.trans.shared.b16 {%0,%1}, [%2];\n"
                 : "=r"(r0), "=r"(r1) : "r"(addr));
}
__device__ __forceinline__ void mma16816(float &c0, float &c1, float &c2, float &c3,
                                         unsigned a0, unsigned a1, unsigned a2, unsigned a3,
                                         unsigned b0, unsigned b1) {
    asm volatile("mma.sync.aligned.m16n8k16.row.col.f32.f16.f16.f32 "
                 "{%0,%1,%2,%3},{%4,%5,%6,%7},{%8,%9},{%0,%1,%2,%3};\n"
                 : "+f"(c0), "+f"(c1), "+f"(c2), "+f"(c3)
                 : "r"(a0), "r"(a1), "r"(a2), "r"(a3), "r"(b0), "r"(b1));
}

// fold one uint4 of half2 pairs into fp32 acc (8 cvt + 8 add)
__device__ __forceinline__ void fold8(float* acc, uint4 v) {
    float2 f;
    f = __half22float2(*(__half2*)&v.x); acc[0] += f.x; acc[1] += f.y;
    f = __half22float2(*(__half2*)&v.y); acc[2] += f.x; acc[3] += f.y;
    f = __half22float2(*(__half2*)&v.z); acc[4] += f.x; acc[5] += f.y;
    f = __half22float2(*(__half2*)&v.w); acc[6] += f.x; acc[7] += f.y;
}
// fp16 pairwise add of two uint4s (4 HADD2)
__device__ __forceinline__ uint4 hadd4(uint4 a, uint4 b) {
    uint4 r;
    *(__half2*)&r.x = __hadd2(*(__half2*)&a.x, *(__half2*)&b.x);
    *(__half2*)&r.y = __hadd2(*(__half2*)&a.y, *(__half2*)&b.y);
    *(__half2*)&r.z = __hadd2(*(__half2*)&a.z, *(__half2*)&b.z);
    *(__half2*)&r.w = __hadd2(*(__half2*)&a.w, *(__half2*)&b.w);
    return r;
}

// ---------------- fused layer: u = D^-1/2(A+I)D^-1/2 x ; y = uW + b ----------------
// Block: 256 threads, 32 nodes. Gather (8 thr/node) -> smem -> in-block HMMA.
template <int FINAL>
__global__ __launch_bounds__(256) void k_layer(const __half* __restrict__ xp,
                                               const __half* __restrict__ W16,
                                               const float* __restrict__ b,
                                               void* __restrict__ outv) {
    __shared__ __align__(16) __half Us[32 * US_LD];
    __shared__ __align__(16) __half Ws[64 * WS_LD];
    int tid = threadIdx.x;
    int node0 = blockIdx.x * 32;

    // raw copy of pre-converted fp16 W (identical padded layout): 576 uint4
    {
        const uint4* Wv = (const uint4*)W16;
        uint4* Sv = (uint4*)Ws;
        #pragma unroll
        for (int i = tid; i < 576; i += 256) Sv[i] = Wv[i];
    }

    // ---- gather phase: 8 threads per node ----
    {
        int group = tid >> 3;            // 0..31
        int lane  = tid & 7;
        int node  = node0 + group;       // NN % 32 == 0
        int cnt = __ldg(&g_cnt[node]);
        int len = cnt < SLOT ? cnt : SLOT;
        const int* cs = &g_csrc[node << 6];
        const uint4* hv = (const uint4*)xp;

        float acc[8];
        #pragma unroll
        for (int i = 0; i < 8; i++) acc[i] = 0.f;
        fold8(acc, __ldg(&hv[((size_t)node << 3) + lane]));   // self term x'[d]

        int e = 0;
        #pragma unroll 2
        for (; e + 4 <= len; e += 4) {
            int4 i4 = __ldg((const int4*)&cs[e]);             // 16B-aligned
            uint4 v0 = __ldg(&hv[((size_t)i4.x << 3) + lane]);
            uint4 v1 = __ldg(&hv[((size_t)i4.y << 3) + lane]);
            uint4 v2 = __ldg(&hv[((size_t)i4.z << 3) + lane]);
            uint4 v3 = __ldg(&hv[((size_t)i4.w << 3) + lane]);
            fold8(acc, hadd4(hadd4(v0, v1), hadd4(v2, v3)));  // 2-level fp16 tree
        }
        if (e + 2 <= len) {
            int a0 = __ldg(&cs[e]);
            int a1 = __ldg(&cs[e + 1]);
            uint4 v0 = __ldg(&hv[((size_t)a0 << 3) + lane]);
            uint4 v1 = __ldg(&hv[((size_t)a1 << 3) + lane]);
            fold8(acc, hadd4(v0, v1));
            e += 2;
        }
        if (e < len) {
            int a = __ldg(&cs[e]);
            fold8(acc, __ldg(&hv[((size_t)a << 3) + lane]));
        }

        float dv = rsqrtf((float)cnt + 1.0f);
        uint4 u;
        u.x = pk2(dv * acc[0], dv * acc[1]);
        u.y = pk2(dv * acc[2], dv * acc[3]);
        u.z = pk2(dv * acc[4], dv * acc[5]);
        u.w = pk2(dv * acc[6], dv * acc[7]);
        *(uint4*)&Us[group * US_LD + lane * 8] = u;
    }
    __syncthreads();

    // ---- matmul phase: 8 warps, warp = 16 rows x 16 cols ----
    int warp = tid >> 5, lane = tid & 31;
    int m0 = (warp & 1) * 16;
    int c0col = (warp >> 1) * 16;
    int g = lane >> 2, tig = lane & 3;

    unsigned us_base = (unsigned)__cvta_generic_to_shared(Us);
    unsigned ws_base = (unsigned)__cvta_generic_to_shared(Ws);

    float c[2][4];
    c[0][0] = c[0][1] = c[0][2] = c[0][3] = 0.f;
    c[1][0] = c[1][1] = c[1][2] = c[1][3] = 0.f;

    #pragma unroll
    for (int kc = 0; kc < 4; kc++) {
        unsigned a0, a1, a2, a3;
        unsigned aaddr = us_base + (m0 + (lane & 15)) * (US_LD * 2) + kc * 32 + (lane >> 4) * 16;
        ldsm_x4(a0, a1, a2, a3, aaddr);
        #pragma unroll
        for (int nt = 0; nt < 2; nt++) {
            unsigned b0, b1;
            unsigned baddr = ws_base + (kc * 16 + (lane & 15)) * (WS_LD * 2) + (c0col + nt * 8) * 2;
            ldsm_x2_t(b0, b1, baddr);
            mma16816(c[nt][0], c[nt][1], c[nt][2], c[nt][3], a0, a1, a2, a3, b0, b1);
        }
    }

    // ---- epilogue ----
    int r0 = node0 + m0 + g;
    int r1 = r0 + 8;
    if (FINAL) {
        float* out = (float*)outv;
        #pragma unroll
        for (int nt = 0; nt < 2; nt++) {
            int col = c0col + nt * 8 + tig * 2;
            float b0v = __ldg(&b[col]), b1v = __ldg(&b[col + 1]);
            *(float2*)&out[(size_t)r0 * DD + col] = make_float2(c[nt][0] + b0v, c[nt][1] + b1v);
            *(float2*)&out[(size_t)r1 * DD + col] = make_float2(c[nt][2] + b0v, c[nt][3] + b1v);
        }
    } else {
        __half* out = (__half*)outv;
        float dv0 = rsqrtf((float)__ldg(&g_cnt[r0]) + 1.0f);
        float dv1 = rsqrtf((float)__ldg(&g_cnt[r1]) + 1.0f);
        #pragma unroll
        for (int nt = 0; nt < 2; nt++) {
            int col = c0col + nt * 8 + tig * 2;
            float b0v = __ldg(&b[col]), b1v = __ldg(&b[col + 1]);
            float v00 = fmaxf(c[nt][0] + b0v, 0.f), v01 = fmaxf(c[nt][1] + b1v, 0.f);
            float v10 = fmaxf(c[nt][2] + b0v, 0.f), v11 = fmaxf(c[nt][3] + b1v, 0.f);
            *(unsigned*)&out[(size_t)r0 * DD + col] = pk2(dv0 * v00, dv0 * v01);
            *(unsigned*)&out[(size_t)r1 * DD + col] = pk2(dv1 * v10, dv1 * v11);
        }
    }
}

// ---------------- launch ----------------
extern "C" void kernel_launch(void* const* d_in, const int* in_sizes, int n_in,
                              void* d_out, int out_size) {
    const float* z   = (const float*)d_in[0];
    const int*   src = (const int*)d_in[1];
    const int*   dst = (const int*)d_in[2];
    const float* W1  = (const float*)d_in[3];
    const float* b1  = (const float*)d_in[4];
    const float* W2  = (const float*)d_in[5];
    const float* b2  = (const float*)d_in[6];
    const float* W3  = (const float*)d_in[7];
    const float* b3  = (const float*)d_in[8];
    float* out = (float*)d_out;

    __half *xa, *xb, *w16; int* cntp;
    cudaGetSymbolAddress((void**)&xa,   g_xa);
    cudaGetSymbolAddress((void**)&xb,   g_xb);
    cudaGetSymbolAddress((void**)&cntp, g_cnt);
    cudaGetSymbolAddress((void**)&w16,  g_w16);

    const int gridFill = (NE / 4 + 255) / 256;      // 1563
    const int gridPS   = (NN * 8 + 255) / 256;      // 3125
    const int gridL    = NN / 32;                   // 3125

    cudaMemsetAsync(cntp, 0, NN * sizeof(int));
    k_wcvt<<<3, 256>>>(W1, W2, W3);
    k_fill<<<gridFill, 256>>>(src, dst);
    k_prescale<<<gridPS, 256>>>(z, xa);

    k_layer<0><<<gridL, 256>>>(xa, w16 + 0 * 64 * WS_LD, b1, xb);
    k_layer<0><<<gridL, 256>>>(xb, w16 + 1 * 64 * WS_LD, b2, xa);
    k_layer<1><<<gridL, 256>>>(xa, w16 + 2 * 64 * WS_LD, b3, out);
}

// round 11
// speedup vs baseline: 1.9919x; 1.0464x over previous
#include <cuda_runtime.h>
#include <cuda_fp16.h>

#define NN 100000
#define NE 1600000
#define DD 64
#define SLOT 64          // fixed edge slots per node; P(deg>64) ~ 1e-19

#define US_LD 72   // halves per row; 144B stride -> conflict-free ldmatrix
#define WS_LD 72
#define NPB 64     // nodes per block
#define NNP 100032 // NN padded to multiple of 64 (100032 = 1563*64)

// ---- scratch (static device globals; no allocation) ----
// padded so the tail block can read/write rows [100000, 100032) harmlessly
__device__ __half g_xa[NNP * DD];        // prescaled activations x' = dinv*x (ping)
__device__ __half g_xb[NNP * DD];        // (pong)
__device__ int    g_cnt[NNP];            // in-degree (pad rows stay 0)
__device__ int    g_csrc[NNP * SLOT];    // src ids bucketed by dst
__device__ __half g_w16[3][64 * WS_LD];  // W in fp16, padded ldmatrix layout
__device__ float  g_pad_out[NPB * DD];   // dump target for pad rows in FINAL layer

__device__ __forceinline__ unsigned pk2(float a, float b) {
    __half2 h = __floats2half2_rn(a, b);
    return *reinterpret_cast<unsigned*>(&h);
}

// ---------------- fill: bucket src ids by dst ----------------
__global__ __launch_bounds__(256) void k_fill(const int* __restrict__ src,
                                              const int* __restrict__ dst) {
    int i = blockIdx.x * blockDim.x + threadIdx.x;
    int e0 = i * 4;
    if (e0 + 3 < NE) {
        int4 s4 = *(const int4*)(src + e0);
        int4 d4 = *(const int4*)(dst + e0);
        int p;
        p = atomicAdd(&g_cnt[d4.x], 1); if (p < SLOT) g_csrc[(d4.x << 6) + p] = s4.x;
        p = atomicAdd(&g_cnt[d4.y], 1); if (p < SLOT) g_csrc[(d4.y << 6) + p] = s4.y;
        p = atomicAdd(&g_cnt[d4.z], 1); if (p < SLOT) g_csrc[(d4.z << 6) + p] = s4.z;
        p = atomicAdd(&g_cnt[d4.w], 1); if (p < SLOT) g_csrc[(d4.w << 6) + p] = s4.w;
    } else {
        for (int e = e0; e < NE; e++) {
            int d = dst[e];
            int p = atomicAdd(&g_cnt[d], 1);
            if (p < SLOT) g_csrc[(d << 6) + p] = src[e];
        }
    }
}

// ---------------- W convert: 3x (64x64 fp32 -> padded [64][72] fp16) ----------------
__global__ __launch_bounds__(256) void k_wcvt(const float* __restrict__ W1,
                                              const float* __restrict__ W2,
                                              const float* __restrict__ W3) {
    const float* Wsrc = (blockIdx.x == 0) ? W1 : (blockIdx.x == 1) ? W2 : W3;
    __half* Wdst = g_w16[blockIdx.x];
    for (int i = threadIdx.x; i < 512; i += 256) {
        int r = i >> 3, cg = i & 7;
        const float4* wp = (const float4*)(Wsrc + r * 64 + cg * 8);
        float4 lo = __ldg(wp), hi = __ldg(wp + 1);
        uint4 v;
        v.x = pk2(lo.x, lo.y); v.y = pk2(lo.z, lo.w);
        v.z = pk2(hi.x, hi.y); v.w = pk2(hi.z, hi.w);
        *(uint4*)&Wdst[r * WS_LD + cg * 8] = v;
    }
}

// ---------------- prescale: x' = dinv * z (fp32 -> fp16); zero pad rows ----------------
__global__ __launch_bounds__(256) void k_prescale(const float* __restrict__ z,
                                                  __half* __restrict__ xp) {
    int i = blockIdx.x * blockDim.x + threadIdx.x;   // one uint4 (8 halves) per thread
    if (i >= NNP * 8) return;
    int node = i >> 3;
    if (node >= NN) { ((uint4*)xp)[i] = make_uint4(0, 0, 0, 0); return; }
    float dv = rsqrtf((float)__ldg(&g_cnt[node]) + 1.0f);
    const float4* zp = (const float4*)(z + (size_t)i * 8);
    float4 lo = __ldg(zp), hi = __ldg(zp + 1);
    uint4 v;
    v.x = pk2(dv * lo.x, dv * lo.y); v.y = pk2(dv * lo.z, dv * lo.w);
    v.z = pk2(dv * hi.x, dv * hi.y); v.w = pk2(dv * hi.z, dv * hi.w);
    ((uint4*)xp)[i] = v;
}

// ---------------- MMA helpers ----------------
__device__ __forceinline__ void ldsm_x4(unsigned &r0, unsigned &r1, unsigned &r2, unsigned &r3, unsigned addr) {
    asm volatile("ldmatrix.sync.aligned.m8n8.x4.shared.b16 {%0,%1,%2,%3}, [%4];\n"
                 : "=r"(r0), "=r"(r1), "=r"(r2), "=r"(r3) : "r"(addr));
}
__device__ __forceinline__ void ldsm_x2_t(unsigned &r0, unsigned &r1, unsigned addr) {
    asm volatile("ldmatrix.sync.aligned.m8n8.x2.trans.shared.b16 {%0,%1}, [%2];\n"
                 : "=r"(r0), "=r"(r1) : "r"(addr));
}
__device__ __forceinline__ void mma16816(float &c0, float &c1, float &c2, float &c3,
                                         unsigned a0, unsigned a1, unsigned a2, unsigned a3,
                                         unsigned b0, unsigned b1) {
    asm volatile("mma.sync.aligned.m16n8k16.row.col.f32.f16.f16.f32 "
                 "{%0,%1,%2,%3},{%4,%5,%6,%7},{%8,%9},{%0,%1,%2,%3};\n"
                 : "+f"(c0), "+f"(c1), "+f"(c2), "+f"(c3)
                 : "r"(a0), "r"(a1), "r"(a2), "r"(a3), "r"(b0), "r"(b1));
}

// fold one uint4 of half2 pairs into fp32 acc (8 cvt + 8 add)
__device__ __forceinline__ void fold8(float* acc, uint4 v) {
    float2 f;
    f = __half22float2(*(__half2*)&v.x); acc[0] += f.x; acc[1] += f.y;
    f = __half22float2(*(__half2*)&v.y); acc[2] += f.x; acc[3] += f.y;
    f = __half22float2(*(__half2*)&v.z); acc[4] += f.x; acc[5] += f.y;
    f = __half22float2(*(__half2*)&v.w); acc[6] += f.x; acc[7] += f.y;
}
// fp16 pairwise add of two uint4s (4 HADD2)
__device__ __forceinline__ uint4 hadd4(uint4 a, uint4 b) {
    uint4 r;
    *(__half2*)&r.x = __hadd2(*(__half2*)&a.x, *(__half2*)&b.x);
    *(__half2*)&r.y = __hadd2(*(__half2*)&a.y, *(__half2*)&b.y);
    *(__half2*)&r.z = __hadd2(*(__half2*)&a.z, *(__half2*)&b.z);
    *(__half2*)&r.w = __hadd2(*(__half2*)&a.w, *(__half2*)&b.w);
    return r;
}

// per-node gather into fp32 acc (8 lanes/node), writes one Us row
__device__ __forceinline__ void gather_node(const uint4* __restrict__ hv, int node,
                                            int lane, __half* __restrict__ Us, int urow) {
    int cnt = __ldg(&g_cnt[node]);          // pad rows: cnt=0 -> only self term (zeros)
    int len = cnt < SLOT ? cnt : SLOT;
    const int* cs = &g_csrc[node << 6];

    float acc[8];
    #pragma unroll
    for (int i = 0; i < 8; i++) acc[i] = 0.f;
    fold8(acc, __ldg(&hv[((size_t)node << 3) + lane]));   // self term x'[d]

    int e = 0;
    #pragma unroll 2
    for (; e + 4 <= len; e += 4) {
        int4 i4 = __ldg((const int4*)&cs[e]);             // 16B-aligned
        uint4 v0 = __ldg(&hv[((size_t)i4.x << 3) + lane]);
        uint4 v1 = __ldg(&hv[((size_t)i4.y << 3) + lane]);
        uint4 v2 = __ldg(&hv[((size_t)i4.z << 3) + lane]);
        uint4 v3 = __ldg(&hv[((size_t)i4.w << 3) + lane]);
        fold8(acc, hadd4(hadd4(v0, v1), hadd4(v2, v3)));  // 2-level fp16 tree
    }
    if (e + 2 <= len) {
        int a0 = __ldg(&cs[e]);
        int a1 = __ldg(&cs[e + 1]);
        uint4 v0 = __ldg(&hv[((size_t)a0 << 3) + lane]);
        uint4 v1 = __ldg(&hv[((size_t)a1 << 3) + lane]);
        fold8(acc, hadd4(v0, v1));
        e += 2;
    }
    if (e < len) {
        int a = __ldg(&cs[e]);
        fold8(acc, __ldg(&hv[((size_t)a << 3) + lane]));
    }

    float dv = rsqrtf((float)cnt + 1.0f);
    uint4 u;
    u.x = pk2(dv * acc[0], dv * acc[1]);
    u.y = pk2(dv * acc[2], dv * acc[3]);
    u.z = pk2(dv * acc[4], dv * acc[5]);
    u.w = pk2(dv * acc[6], dv * acc[7]);
    *(uint4*)&Us[urow * US_LD + lane * 8] = u;
}

// ---------------- fused layer: u = D^-1/2(A+I)D^-1/2 x ; y = uW + b ----------------
// Block: 256 threads, 64 nodes (2 sequential per 8-lane group). In-block HMMA:
// 8 warps x 2 M-tiles of 16x16. Pad rows (>= NN) are zeros; FINAL pad writes
// go to g_pad_out.
template <int FINAL>
__global__ __launch_bounds__(256, 6) void k_layer(const __half* __restrict__ xp,
                                                  const __half* __restrict__ W16,
                                                  const float* __restrict__ b,
                                                  void* __restrict__ outv) {
    __shared__ __align__(16) __half Us[NPB * US_LD];
    __shared__ __align__(16) __half Ws[64 * WS_LD];
    int tid = threadIdx.x;
    int node0 = blockIdx.x * NPB;

    // raw copy of pre-converted fp16 W (identical padded layout): 576 uint4
    {
        const uint4* Wv = (const uint4*)W16;
        uint4* Sv = (uint4*)Ws;
        #pragma unroll
        for (int i = tid; i < 576; i += 256) Sv[i] = Wv[i];
    }

    // ---- gather phase ----
    {
        int group = tid >> 3;            // 0..31
        int lane  = tid & 7;
        const uint4* hv = (const uint4*)xp;
        gather_node(hv, node0 + group,      lane, Us, group);
        gather_node(hv, node0 + group + 32, lane, Us, group + 32);
    }
    __syncthreads();

    // ---- matmul phase ----
    int warp = tid >> 5, lane = tid & 31;
    int c0col = (warp >> 1) * 16;
    int g = lane >> 2, tig = lane & 3;

    unsigned us_base = (unsigned)__cvta_generic_to_shared(Us);
    unsigned ws_base = (unsigned)__cvta_generic_to_shared(Ws);

    #pragma unroll
    for (int mi = 0; mi < 2; mi++) {
        int m0 = (warp & 1) * 16 + mi * 32;

        float c[2][4];
        c[0][0] = c[0][1] = c[0][2] = c[0][3] = 0.f;
        c[1][0] = c[1][1] = c[1][2] = c[1][3] = 0.f;

        #pragma unroll
        for (int kc = 0; kc < 4; kc++) {
            unsigned a0, a1, a2, a3;
            unsigned aaddr = us_base + (m0 + (lane & 15)) * (US_LD * 2) + kc * 32 + (lane >> 4) * 16;
            ldsm_x4(a0, a1, a2, a3, aaddr);
            #pragma unroll
            for (int nt = 0; nt < 2; nt++) {
                unsigned b0, b1;
                unsigned baddr = ws_base + (kc * 16 + (lane & 15)) * (WS_LD * 2) + (c0col + nt * 8) * 2;
                ldsm_x2_t(b0, b1, baddr);
                mma16816(c[nt][0], c[nt][1], c[nt][2], c[nt][3], a0, a1, a2, a3, b0, b1);
            }
        }

        int r0 = node0 + m0 + g;
        int r1 = r0 + 8;
        if (FINAL) {
            // pad rows redirect to dump buffer (real out has exactly NN rows)
            float* o0 = (r0 < NN) ? ((float*)outv + (size_t)r0 * DD) : (g_pad_out + (r0 - NN) * DD);
            float* o1 = (r1 < NN) ? ((float*)outv + (size_t)r1 * DD) : (g_pad_out + (r1 - NN) * DD);
            #pragma unroll
            for (int nt = 0; nt < 2; nt++) {
                int col = c0col + nt * 8 + tig * 2;
                float b0v = __ldg(&b[col]), b1v = __ldg(&b[col + 1]);
                *(float2*)&o0[col] = make_float2(c[nt][0] + b0v, c[nt][1] + b1v);
                *(float2*)&o1[col] = make_float2(c[nt][2] + b0v, c[nt][3] + b1v);
            }
        } else {
            __half* out = (__half*)outv;      // sized NNP rows: pad writes OK
            float dv0 = rsqrtf((float)__ldg(&g_cnt[r0]) + 1.0f);
            float dv1 = rsqrtf((float)__ldg(&g_cnt[r1]) + 1.0f);
            #pragma unroll
            for (int nt = 0; nt < 2; nt++) {
                int col = c0col + nt * 8 + tig * 2;
                float b0v = __ldg(&b[col]), b1v = __ldg(&b[col + 1]);
                float v00 = fmaxf(c[nt][0] + b0v, 0.f), v01 = fmaxf(c[nt][1] + b1v, 0.f);
                float v10 = fmaxf(c[nt][2] + b0v, 0.f), v11 = fmaxf(c[nt][3] + b1v, 0.f);
                *(unsigned*)&out[(size_t)r0 * DD + col] = pk2(dv0 * v00, dv0 * v01);
                *(unsigned*)&out[(size_t)r1 * DD + col] = pk2(dv1 * v10, dv1 * v11);
            }
        }
    }
}

// ---------------- launch ----------------
extern "C" void kernel_launch(void* const* d_in, const int* in_sizes, int n_in,
                              void* d_out, int out_size) {
    const float* z   = (const float*)d_in[0];
    const int*   src = (const int*)d_in[1];
    const int*   dst = (const int*)d_in[2];
    const float* W1  = (const float*)d_in[3];
    const float* b1  = (const float*)d_in[4];
    const float* W2  = (const float*)d_in[5];
    const float* b2  = (const float*)d_in[6];
    const float* W3  = (const float*)d_in[7];
    const float* b3  = (const float*)d_in[8];
    float* out = (float*)d_out;

    __half *xa, *xb, *w16; int* cntp;
    cudaGetSymbolAddress((void**)&xa,   g_xa);
    cudaGetSymbolAddress((void**)&xb,   g_xb);
    cudaGetSymbolAddress((void**)&cntp, g_cnt);
    cudaGetSymbolAddress((void**)&w16,  g_w16);

    const int gridFill = (NE / 4 + 255) / 256;      // 1563
    const int gridPS   = (NNP * 8 + 255) / 256;     // 3126
    const int gridL    = NNP / NPB;                 // 1563

    cudaMemsetAsync(cntp, 0, NNP * sizeof(int));    // pad cnt stays 0
    k_wcvt<<<3, 256>>>(W1, W2, W3);
    k_fill<<<gridFill, 256>>>(src, dst);
    k_prescale<<<gridPS, 256>>>(z, xa);             // zeros pad rows of xa

    k_layer<0><<<gridL, 256>>>(xa, w16 + 0 * 64 * WS_LD, b1, xb);
    k_layer<0><<<gridL, 256>>>(xb, w16 + 1 * 64 * WS_LD, b2, xa);
    k_layer<1><<<gridL, 256>>>(xa, w16 + 2 * 64 * WS_LD, b3, out);
}